// round 10
// baseline (speedup 1.0000x reference)
#include <cuda_runtime.h>
#include <math.h>

#define T   65536
#define NCH 32
#define CS  256      // biquad chunk
#define NC  (T/CS)   // 256 chunks
#define RCH 225      // reverb chunk (= min allpass lag)
#define NRC ((T + RCH - 1)/RCH)

__constant__ int c_Lc[8] = {1116,1188,1277,1356,1422,1491,1557,1617};
__constant__ int c_La[4] = {556,441,341,225};

// ------------------------------- scratch -----------------------------------
__device__ float g_buf1[(size_t)NCH*T];   // biquad y -> compressed x (in place)
__device__ float g_buf2[(size_t)NCH*T];   // tgt [t][32] -> reverb out [ch][t]
__device__ float g_buf3[(size_t)NCH*T];   // compressor gain g [t][32]
__device__ float g_cw[(size_t)8*NCH*T];   // comb write timelines
__device__ float g_av[(size_t)4*NCH*T];   // allpass write timelines

__device__ float g_coef[NCH][6][5];       // b0 b1 b2 a1 a2
__device__ float g_P[NCH][144];           // A^256
__device__ float g_gin[NCH];
__device__ float g_cmp[NCH][4];           // cA cB thr slope
__device__ float g_vrb[NCH][4];           // fb damp wet1 dryg
__device__ float g_pg[NCH][2];            // gout*cos gout*sin

// ------------------------------- params ------------------------------------
__device__ void d_shelf(double fc,double g,double s,double*B,double*A){
    const double SR=44100.0, PI=3.14159265358979323846;
    double Aa=pow(10.0,g/40.0), w=2.0*PI*fc/SR, cw=cos(w);
    double al=sin(w)*0.7071067811865476, sq=2.0*sqrt(Aa)*al;
    B[0]=Aa*((Aa+1.0)+s*(Aa-1.0)*cw+sq);
    B[1]=-2.0*s*Aa*((Aa-1.0)+s*(Aa+1.0)*cw);
    B[2]=Aa*((Aa+1.0)+s*(Aa-1.0)*cw-sq);
    A[0]=(Aa+1.0)-s*(Aa-1.0)*cw+sq;
    A[1]=2.0*s*((Aa-1.0)-s*(Aa+1.0)*cw);
    A[2]=(Aa+1.0)-s*(Aa-1.0)*cw-sq;
}
__device__ void d_peak(double fc,double g,double q,double*B,double*A){
    const double SR=44100.0, PI=3.14159265358979323846;
    double Aa=pow(10.0,g/40.0), w=2.0*PI*fc/SR, cw=cos(w), al=sin(w)/(2.0*q);
    B[0]=1.0+al*Aa; B[1]=-2.0*cw; B[2]=1.0-al*Aa;
    A[0]=1.0+al/Aa; A[1]=-2.0*cw; A[2]=1.0-al/Aa;
}

__global__ void k_params(const float* __restrict__ p, float* __restrict__ pout){
    int ch = threadIdx.x; if (ch >= NCH) return;
    const float* pf = p + ch*24;
    const double SR=44100.0, PI=3.14159265358979323846;
    double gin_db=(double)pf[0]*60.0-48.0;
    double hp=(double)pf[1]*350.0, lp=3000.0+(double)pf[2]*19000.0;
    double hsf=1500.0+(double)pf[3]*14500.0, hsg=(double)pf[4]*30.0-15.0;
    double lsf=30.0+(double)pf[5]*420.0,    lsg=(double)pf[6]*30.0-15.0;
    double mhf=600.0+(double)pf[7]*6400.0,  mhg=(double)pf[8]*30.0-15.0, mhq=0.5+(double)pf[9]*2.5;
    double mlf=200.0+(double)pf[10]*2300.0, mlg=(double)pf[11]*30.0-15.0, mlq=0.5+(double)pf[12]*2.5;
    double cth=-20.0+(double)pf[13]*30.0, crt=1.0+(double)pf[14]*19.0;
    double cat=1.0+(double)pf[15]*29.0,   crl=100.0+(double)pf[16]*3900.0;
    double god=(double)pf[22]*60.0-48.0,  pan=0.3+(double)pf[23]*0.4;

    double B[6][3], A[6][3];
    { double K=tan(PI*hp/SR),a1=(K-1.0)/(K+1.0),b0=1.0/(1.0+K);
      B[0][0]=b0;B[0][1]=-b0;B[0][2]=0;A[0][0]=1;A[0][1]=a1;A[0][2]=0; }
    { double K=tan(PI*lp/SR),a1=(K-1.0)/(K+1.0),b0=K/(1.0+K);
      B[1][0]=b0;B[1][1]=b0;B[1][2]=0;A[1][0]=1;A[1][1]=a1;A[1][2]=0; }
    d_shelf(hsf,hsg, 1.0,B[2],A[2]);
    d_shelf(lsf,lsg,-1.0,B[3],A[3]);
    d_peak (mhf,mhg,mhq,B[4],A[4]);
    d_peak (mlf,mlg,mlq,B[5],A[5]);

    double nb[6][3], na[6][2];
    for (int s=0;s<6;s++){
        double a0=A[s][0];
        float b0=(float)(B[s][0]/a0),b1=(float)(B[s][1]/a0),b2=(float)(B[s][2]/a0);
        float a1=(float)(A[s][1]/a0),a2=(float)(A[s][2]/a0);
        g_coef[ch][s][0]=b0;g_coef[ch][s][1]=b1;g_coef[ch][s][2]=b2;
        g_coef[ch][s][3]=a1;g_coef[ch][s][4]=a2;
        nb[s][0]=b0;nb[s][1]=b1;nb[s][2]=b2;na[s][0]=a1;na[s][1]=a2;
    }
    // one-step 12x12 state map via unit vectors (input = 0)
    float M[144], Tm[144];
    for (int k=0;k<12;k++){
        double z[12]; for(int i=0;i<12;i++) z[i]=0.0; z[k]=1.0;
        double s=0.0;
        for (int sc=0;sc<6;sc++){
            double y =nb[sc][0]*s+z[2*sc];
            double z1=nb[sc][1]*s-na[sc][0]*y+z[2*sc+1];
            double z2=nb[sc][2]*s-na[sc][1]*y;
            z[2*sc]=z1; z[2*sc+1]=z2; s=y;
        }
        for (int r=0;r<12;r++) M[r*12+k]=(float)z[r];
    }
    for (int it=0; it<8; it++){       // M = M^2, 8x -> A^256
        for (int r=0;r<12;r++) for(int c=0;c<12;c++){
            float acc=0.f;
            for (int k=0;k<12;k++) acc=fmaf(M[r*12+k],M[k*12+c],acc);
            Tm[r*12+c]=acc;
        }
        for (int i=0;i<144;i++) M[i]=Tm[i];
    }
    for (int i=0;i<144;i++) g_P[ch][i]=M[i];

    g_gin[ch]=(float)pow(10.0,gin_db/20.0);
    double aat=exp(-1.0/(cat*0.001*SR)), arl=exp(-1.0/(crl*0.001*SR));
    g_cmp[ch][0]=(float)((aat+arl)*0.5);
    g_cmp[ch][1]=(float)((aat-arl)*0.5);
    g_cmp[ch][2]=(float)cth;
    g_cmp[ch][3]=(float)(1.0-1.0/crt);

    g_vrb[ch][0]=(float)((double)pf[17]*0.28+0.7);
    g_vrb[ch][1]=(float)((double)pf[18]*0.4);
    g_vrb[ch][2]=(float)(3.0*(double)pf[19]*0.5*(1.0+(double)pf[21]));
    g_vrb[ch][3]=(float)(2.0*(double)pf[20]);

    double gol=pow(10.0,god/20.0), th=pan*PI*0.5;
    g_pg[ch][0]=(float)(gol*cos(th));
    g_pg[ch][1]=(float)(gol*sin(th));

    if (pout){
        float* po=pout+ch*24;
        po[0]=(float)gin_db; po[1]=(float)hp; po[2]=(float)lp; po[3]=(float)hsf;
        po[4]=(float)hsg; po[5]=(float)lsf; po[6]=(float)lsg; po[7]=(float)mhf;
        po[8]=(float)mhg; po[9]=(float)mhq; po[10]=(float)mlf; po[11]=(float)mlg;
        po[12]=(float)mlq; po[13]=(float)cth; po[14]=(float)crt; po[15]=(float)cat;
        po[16]=(float)crl; po[17]=pf[17]; po[18]=pf[18]; po[19]=pf[19];
        po[20]=pf[20]; po[21]=pf[21]; po[22]=(float)god; po[23]=(float)pan;
    }
}

// --------------------------- biquad blocked scan ----------------------------
__device__ __forceinline__ float bq6(float s, float z[12], const float c[6][5]){
#pragma unroll
    for (int k=0;k<6;k++){
        float y  = fmaf(c[k][0], s, z[2*k]);
        float z1 = fmaf(c[k][1], s, z[2*k+1]) - c[k][3]*y;
        z[2*k+1] = fmaf(c[k][2], s, -(c[k][4]*y));
        z[2*k]   = z1;
        s = y;
    }
    return s;
}

__global__ void __launch_bounds__(256) k_biquad(const float* __restrict__ x){
    __shared__ float sF[NC][12];
    __shared__ float sI[NC][12];
    int ch = blockIdx.x, tid = threadIdx.x;
    float c[6][5];
#pragma unroll
    for (int k=0;k<6;k++)
#pragma unroll
        for (int j=0;j<5;j++) c[k][j]=g_coef[ch][k][j];
    float gin = g_gin[ch];
    float thr = g_cmp[ch][2], slope = g_cmp[ch][3];
    const float4* xc = (const float4*)(x + (size_t)ch*T) + tid*(CS/4);

    float z[12];
#pragma unroll
    for (int i=0;i<12;i++) z[i]=0.f;
    for (int i=0;i<CS/4;i++){
        float4 v = xc[i];
        bq6(v.x*gin,z,c); bq6(v.y*gin,z,c); bq6(v.z*gin,z,c); bq6(v.w*gin,z,c);
    }
#pragma unroll
    for (int i=0;i<12;i++) sF[tid][i]=z[i];
    __syncthreads();

    if (tid < 12){
        int r = tid;
        float Pr[12];
#pragma unroll
        for (int k=0;k<12;k++) Pr[k]=g_P[ch][r*12+k];
        sI[0][r]=0.f;
        __syncwarp(0xFFFu);
        for (int j=0;j<NC-1;j++){
            float acc = sF[j][r];
#pragma unroll
            for (int k=0;k<12;k++) acc = fmaf(Pr[k], sI[j][k], acc);
            __syncwarp(0xFFFu);
            sI[j+1][r]=acc;
            __syncwarp(0xFFFu);
        }
    }
    __syncthreads();

#pragma unroll
    for (int i=0;i<12;i++) z[i]=sI[tid][i];
    int t0 = tid*CS;
    float* yb = g_buf1 + (size_t)ch*T + t0;
    for (int i=0;i<CS/4;i++){
        float4 v = xc[i];
        float y0=bq6(v.x*gin,z,c), y1=bq6(v.y*gin,z,c);
        float y2=bq6(v.z*gin,z,c), y3=bq6(v.w*gin,z,c);
        ((float4*)yb)[i] = make_float4(y0,y1,y2,y3);
        float ys[4]={y0,y1,y2,y3};
#pragma unroll
        for (int q=0;q<4;q++){
            float lvl = __log2f(fabsf(ys[q]) + 1e-6f) * 6.0205999132796239f;
            float tg  = fminf(0.f, (thr - lvl)*slope);
            g_buf2[(size_t)(t0 + i*4 + q)*32 + ch] = tg;
        }
    }
}

// ------------------------------ compressor ---------------------------------
__global__ void k_comp(){
    int ch = threadIdx.x;
    float cA = g_cmp[ch][0], cB = g_cmp[ch][1];
    const float* tg = g_buf2;
    float* go = g_buf3;
    float buf[2][33];
#pragma unroll
    for (int i=0;i<33;i++) buf[0][i] = tg[(size_t)i*32 + ch];
    float d = -buf[0][0];
    int cur = 0;
    const int NB = T/32;
    for (int blk=0; blk<NB; blk++){
        int nxt = cur^1;
        if (blk+1 < NB){
            size_t b2 = (size_t)(blk+1)*32;
#pragma unroll
            for (int i=0;i<33;i++){
                size_t t = b2 + i;
                buf[nxt][i] = (t < T) ? tg[t*32 + ch] : 0.f;
            }
        }
        float st[32];
#pragma unroll
        for (int i=0;i<32;i++){
            float tk = buf[cur][i], tn = buf[cur][i+1];
            float e = cB*d;
            float f = (tk - tn) - fabsf(e);
            d = fmaf(cA, d, f);
            st[i] = d + tn;
        }
        size_t b0 = (size_t)blk*32;
#pragma unroll
        for (int i=0;i<32;i++) go[(b0+i)*32 + ch] = st[i];
        cur = nxt;
    }
}

// -------------------------------- freeverb ---------------------------------
__global__ void __launch_bounds__(256) k_reverb(){
    int ch = blockIdx.x, tid = threadIdx.x;
    float fb   = g_vrb[ch][0], damp = g_vrb[ch][1];
    float wet1 = g_vrb[ch][2], dryg = g_vrb[ch][3];
    float fbd  = fb*(1.f - damp);
    const float K2 = 0.16609640474436813f; // log2(10)/20

    for (int c=0; c<NRC; c++){
        int t = c*RCH + tid;
        if (tid < RCH && t < T){
            float xc = g_buf1[(size_t)ch*T + t] * exp2f(g_buf3[(size_t)t*32 + ch]*K2);
            g_buf1[(size_t)ch*T + t] = xc;
            float inp = xc*0.015f;
            float acc = 0.f;
#pragma unroll
            for (int k=0;k<8;k++){
                float* w = g_cw + ((size_t)k*NCH + ch)*T;
                int b = t - c_Lc[k];
                float s = 0.f, outv = 0.f;
#pragma unroll
                for (int j=15;j>=0;j--){
                    int idx = b - j;
                    float wv = (idx >= 0) ? w[idx] : 0.f;
                    s = fmaf(s, damp, wv);
                    if (j==0) outv = wv;
                }
                acc += outv;
                w[t] = fmaf(fbd, s, inp);
            }
#pragma unroll
            for (int k=0;k<4;k++){
                float* v = g_av + ((size_t)k*NCH + ch)*T;
                int b = t - c_La[k];
                float bufv = (b >= 0) ? v[b] : 0.f;
                v[t] = fmaf(bufv, 0.5f, acc);
                acc = bufv - acc;
            }
            g_buf2[(size_t)ch*T + t] = acc*wet1 + xc*dryg;
        }
        __syncthreads();
    }
}

// --------------------------------- mix -------------------------------------
__global__ void k_mix(float* __restrict__ out){
    int idx = blockIdx.x*blockDim.x + threadIdx.x;   // over 4*T
    if (idx >= 4*T) return;
    int b = idx / T, t = idx - b*T;
    float l=0.f, r=0.f;
#pragma unroll
    for (int n=0;n<8;n++){
        int ch = b*8 + n;
        float v = g_buf2[(size_t)ch*T + t];
        l = fmaf(v, g_pg[ch][0], l);
        r = fmaf(v, g_pg[ch][1], r);
    }
    out[((size_t)(b*2+0))*T + t] = l;
    out[((size_t)(b*2+1))*T + t] = r;
}

// -------------------------------- launch ------------------------------------
extern "C" void kernel_launch(void* const* d_in, const int* in_sizes, int n_in,
                              void* d_out, int out_size){
    const float* x = (const float*)d_in[0];
    const float* p = (const float*)d_in[1];
    if (n_in >= 2 && in_sizes[0] < in_sizes[1]) { // defensive: x is the big one
        const float* tmp = x; x = p; p = tmp;
    }
    float* out  = (float*)d_out;
    float* pout = (out_size >= 4*2*T + 4*8*24) ? out + (size_t)4*2*T : nullptr;

    k_params<<<1, 32>>>(p, pout);
    k_biquad<<<NCH, 256>>>(x);
    k_comp<<<1, 32>>>();
    k_reverb<<<NCH, 256>>>();
    k_mix<<<(4*T + 255)/256, 256>>>(out);
}

// round 13
// speedup vs baseline: 2.1035x; 2.1035x over previous
#include <cuda_runtime.h>
#include <math.h>

#define T    65536
#define NCH  32
#define CS   256        // biquad chunk
#define NC   (T/CS)     // 256 chunks
#define RCH  224        // reverb chunk (7 warps, <= min allpass lag 225)
#define NRC  ((T + RCH - 1)/RCH)   // 293
#define NTAP 16         // damp FIR taps (0.4^16 = 4.3e-7)

// ------------------------------- scratch -----------------------------------
__device__ float g_buf1[(size_t)NCH*T];              // biquad y [ch][t]
__device__ float g_buf2[(size_t)NCH*T + 32*68];      // tgt [t][32] (+pad) -> reverb out [ch][t]
__device__ float g_buf3[(size_t)NCH*T];              // compressor gain g [t][32]

__device__ float g_coef[NCH][6][5];            // b0 b1 b2 a1 a2
__device__ float g_P[NCH][144];                // A^256
__device__ float g_gin[NCH];
__device__ float g_cmp[NCH][4];                // a_att a_rel thr slope
__device__ float g_vrb[NCH][4];                // fb damp wet1 dryg
__device__ float g_pg[NCH][2];                 // gout*cos gout*sin

// ------------------------------- params ------------------------------------
__device__ void d_shelf(double fc,double g,double s,double*B,double*A){
    const double SR=44100.0, PI=3.14159265358979323846;
    double Aa=pow(10.0,g/40.0), w=2.0*PI*fc/SR, cw=cos(w);
    double al=sin(w)*0.7071067811865476, sq=2.0*sqrt(Aa)*al;
    B[0]=Aa*((Aa+1.0)+s*(Aa-1.0)*cw+sq);
    B[1]=-2.0*s*Aa*((Aa-1.0)+s*(Aa+1.0)*cw);
    B[2]=Aa*((Aa+1.0)+s*(Aa-1.0)*cw-sq);
    A[0]=(Aa+1.0)-s*(Aa-1.0)*cw+sq;
    A[1]=2.0*s*((Aa-1.0)-s*(Aa+1.0)*cw);
    A[2]=(Aa+1.0)-s*(Aa-1.0)*cw-sq;
}
__device__ void d_peak(double fc,double g,double q,double*B,double*A){
    const double SR=44100.0, PI=3.14159265358979323846;
    double Aa=pow(10.0,g/40.0), w=2.0*PI*fc/SR, cw=cos(w), al=sin(w)/(2.0*q);
    B[0]=1.0+al*Aa; B[1]=-2.0*cw; B[2]=1.0-al*Aa;
    A[0]=1.0+al/Aa; A[1]=-2.0*cw; A[2]=1.0-al/Aa;
}

__global__ void k_params(const float* __restrict__ p, float* __restrict__ pout){
    int ch = threadIdx.x; if (ch >= NCH) return;
    const float* pf = p + ch*24;
    const double SR=44100.0, PI=3.14159265358979323846;
    double gin_db=(double)pf[0]*60.0-48.0;
    double hp=(double)pf[1]*350.0, lp=3000.0+(double)pf[2]*19000.0;
    double hsf=1500.0+(double)pf[3]*14500.0, hsg=(double)pf[4]*30.0-15.0;
    double lsf=30.0+(double)pf[5]*420.0,    lsg=(double)pf[6]*30.0-15.0;
    double mhf=600.0+(double)pf[7]*6400.0,  mhg=(double)pf[8]*30.0-15.0, mhq=0.5+(double)pf[9]*2.5;
    double mlf=200.0+(double)pf[10]*2300.0, mlg=(double)pf[11]*30.0-15.0, mlq=0.5+(double)pf[12]*2.5;
    double cth=-20.0+(double)pf[13]*30.0, crt=1.0+(double)pf[14]*19.0;
    double cat=1.0+(double)pf[15]*29.0,   crl=100.0+(double)pf[16]*3900.0;
    double god=(double)pf[22]*60.0-48.0,  pan=0.3+(double)pf[23]*0.4;

    double B[6][3], A[6][3];
    { double K=tan(PI*hp/SR),a1=(K-1.0)/(K+1.0),b0=1.0/(1.0+K);
      B[0][0]=b0;B[0][1]=-b0;B[0][2]=0;A[0][0]=1;A[0][1]=a1;A[0][2]=0; }
    { double K=tan(PI*lp/SR),a1=(K-1.0)/(K+1.0),b0=K/(1.0+K);
      B[1][0]=b0;B[1][1]=b0;B[1][2]=0;A[1][0]=1;A[1][1]=a1;A[1][2]=0; }
    d_shelf(hsf,hsg, 1.0,B[2],A[2]);
    d_shelf(lsf,lsg,-1.0,B[3],A[3]);
    d_peak (mhf,mhg,mhq,B[4],A[4]);
    d_peak (mlf,mlg,mlq,B[5],A[5]);

    double nb[6][3], na[6][2];
    for (int s=0;s<6;s++){
        double a0=A[s][0];
        float b0=(float)(B[s][0]/a0),b1=(float)(B[s][1]/a0),b2=(float)(B[s][2]/a0);
        float a1=(float)(A[s][1]/a0),a2=(float)(A[s][2]/a0);
        g_coef[ch][s][0]=b0;g_coef[ch][s][1]=b1;g_coef[ch][s][2]=b2;
        g_coef[ch][s][3]=a1;g_coef[ch][s][4]=a2;
        nb[s][0]=b0;nb[s][1]=b1;nb[s][2]=b2;na[s][0]=a1;na[s][1]=a2;
    }
    // one-step 12x12 state map via unit vectors (input = 0)
    float M[144], Tm[144];
    for (int k=0;k<12;k++){
        double z[12]; for(int i=0;i<12;i++) z[i]=0.0; z[k]=1.0;
        double s=0.0;
        for (int sc=0;sc<6;sc++){
            double y =nb[sc][0]*s+z[2*sc];
            double z1=nb[sc][1]*s-na[sc][0]*y+z[2*sc+1];
            double z2=nb[sc][2]*s-na[sc][1]*y;
            z[2*sc]=z1; z[2*sc+1]=z2; s=y;
        }
        for (int r=0;r<12;r++) M[r*12+k]=(float)z[r];
    }
    for (int it=0; it<8; it++){       // M = M^2, 8x -> A^256
        for (int r=0;r<12;r++) for(int c=0;c<12;c++){
            float acc=0.f;
            for (int k=0;k<12;k++) acc=fmaf(M[r*12+k],M[k*12+c],acc);
            Tm[r*12+c]=acc;
        }
        for (int i=0;i<144;i++) M[i]=Tm[i];
    }
    for (int i=0;i<144;i++) g_P[ch][i]=M[i];

    g_gin[ch]=(float)pow(10.0,gin_db/20.0);
    g_cmp[ch][0]=(float)exp(-1.0/(cat*0.001*SR));  // a_att
    g_cmp[ch][1]=(float)exp(-1.0/(crl*0.001*SR));  // a_rel
    g_cmp[ch][2]=(float)cth;
    g_cmp[ch][3]=(float)(1.0-1.0/crt);

    g_vrb[ch][0]=(float)((double)pf[17]*0.28+0.7);
    g_vrb[ch][1]=(float)((double)pf[18]*0.4);
    g_vrb[ch][2]=(float)(3.0*(double)pf[19]*0.5*(1.0+(double)pf[21]));
    g_vrb[ch][3]=(float)(2.0*(double)pf[20]);

    double gol=pow(10.0,god/20.0), th=pan*PI*0.5;
    g_pg[ch][0]=(float)(gol*cos(th));
    g_pg[ch][1]=(float)(gol*sin(th));

    g_buf2[(size_t)T*32 + ch] = 0.f;   // tgt pad (t = T)

    if (pout){
        float* po=pout+ch*24;
        po[0]=(float)gin_db; po[1]=(float)hp; po[2]=(float)lp; po[3]=(float)hsf;
        po[4]=(float)hsg; po[5]=(float)lsf; po[6]=(float)lsg; po[7]=(float)mhf;
        po[8]=(float)mhg; po[9]=(float)mhq; po[10]=(float)mlf; po[11]=(float)mlg;
        po[12]=(float)mlq; po[13]=(float)cth; po[14]=(float)crt; po[15]=(float)cat;
        po[16]=(float)crl; po[17]=pf[17]; po[18]=pf[18]; po[19]=pf[19];
        po[20]=pf[20]; po[21]=pf[21]; po[22]=(float)god; po[23]=(float)pan;
    }
}

// --------------------------- biquad blocked scan ----------------------------
__device__ __forceinline__ float bq6(float s, float z[12], const float c[6][5]){
#pragma unroll
    for (int k=0;k<6;k++){
        float y  = fmaf(c[k][0], s, z[2*k]);
        float z1 = fmaf(c[k][1], s, z[2*k+1]) - c[k][3]*y;
        z[2*k+1] = fmaf(c[k][2], s, -(c[k][4]*y));
        z[2*k]   = z1;
        s = y;
    }
    return s;
}

__global__ void __launch_bounds__(256) k_biquad(const float* __restrict__ x){
    __shared__ float sF[NC][12];
    __shared__ float sI[NC][12];
    int ch = blockIdx.x, tid = threadIdx.x;
    float c[6][5];
#pragma unroll
    for (int k=0;k<6;k++)
#pragma unroll
        for (int j=0;j<5;j++) c[k][j]=g_coef[ch][k][j];
    float gin = g_gin[ch];
    float thr = g_cmp[ch][2], slope = g_cmp[ch][3];
    const float4* xc = (const float4*)(x + (size_t)ch*T) + tid*(CS/4);

    float z[12];
#pragma unroll
    for (int i=0;i<12;i++) z[i]=0.f;
    for (int i=0;i<CS/4;i++){
        float4 v = xc[i];
        bq6(v.x*gin,z,c); bq6(v.y*gin,z,c); bq6(v.z*gin,z,c); bq6(v.w*gin,z,c);
    }
#pragma unroll
    for (int i=0;i<12;i++) sF[tid][i]=z[i];
    __syncthreads();

    if (tid < 12){
        int r = tid;
        float Pr[12];
#pragma unroll
        for (int k=0;k<12;k++) Pr[k]=g_P[ch][r*12+k];
        sI[0][r]=0.f;
        __syncwarp(0xFFFu);
        for (int j=0;j<NC-1;j++){
            float acc = sF[j][r];
#pragma unroll
            for (int k=0;k<12;k++) acc = fmaf(Pr[k], sI[j][k], acc);
            __syncwarp(0xFFFu);
            sI[j+1][r]=acc;
            __syncwarp(0xFFFu);
        }
    }
    __syncthreads();

#pragma unroll
    for (int i=0;i<12;i++) z[i]=sI[tid][i];
    int t0 = tid*CS;
    float* yb = g_buf1 + (size_t)ch*T + t0;
    for (int i=0;i<CS/4;i++){
        float4 v = xc[i];
        float y0=bq6(v.x*gin,z,c), y1=bq6(v.y*gin,z,c);
        float y2=bq6(v.z*gin,z,c), y3=bq6(v.w*gin,z,c);
        ((float4*)yb)[i] = make_float4(y0,y1,y2,y3);
        float ys[4]={y0,y1,y2,y3};
#pragma unroll
        for (int q=0;q<4;q++){
            float lvl = __log2f(fabsf(ys[q]) + 1e-6f) * 6.0205999132796239f;
            float tg  = fminf(0.f, (thr - lvl)*slope);
            g_buf2[(size_t)(t0 + i*4 + q)*32 + ch] = tg;
        }
    }
}

// ---------------- compressor: EXACT serial scan, 8-cycle chain ---------------
// e_t = g_{t-1} - tgt_t ; e' = cA*e + cB*|e| + (tgt_t - tgt_{t+1}) ; g_t = e' + tgt_{t+1}
// cA=(aA+aR)/2, cB=(aA-aR)/2 reproduces coef = aA if e>0 else aR exactly.
// All buffers are static register arrays (no dynamic indexing -> no local mem).
__global__ void k_comp(){
    int ch = threadIdx.x;
    float aA = g_cmp[ch][0], aR = g_cmp[ch][1];
    float cA = 0.5f*(aA+aR), cB = 0.5f*(aA-aR);
    const float* __restrict__ tg = g_buf2;
    float* __restrict__ go = g_buf3;

    float bufA[32], bufB[32];
#pragma unroll
    for (int i=0;i<32;i++) bufA[i] = tg[(size_t)(i+1)*32 + ch];
    float cp = tg[ch];        // tgt[0]
    float e  = -cp;           // g_{-1} = 0
    const int NB = T/32;      // 2048 blocks

    for (int blk = 0; blk < NB; blk += 2){
        {   // prefetch blk+1
            size_t base = (size_t)(blk+1)*32 + 1;
#pragma unroll
            for (int i=0;i<32;i++) bufB[i] = tg[(base+i)*32 + ch];
        }
        {   // process blk (bufA)
            float gg[32];
#pragma unroll
            for (int i=0;i<32;i++){
                float tn = bufA[i];
                float d  = cp - tn;
                float f  = fmaf(cB, fabsf(e), d);
                e = fmaf(cA, e, f);
                gg[i] = e + tn;
                cp = tn;
            }
            size_t b0 = (size_t)blk*32;
#pragma unroll
            for (int i=0;i<32;i++) go[(b0+i)*32 + ch] = gg[i];
        }
        {   // prefetch blk+2 (pad guarantees in-bounds)
            size_t base = (size_t)(blk+2)*32 + 1;
#pragma unroll
            for (int i=0;i<32;i++) bufA[i] = tg[(base+i)*32 + ch];
        }
        {   // process blk+1 (bufB)
            float gg[32];
#pragma unroll
            for (int i=0;i<32;i++){
                float tn = bufB[i];
                float d  = cp - tn;
                float f  = fmaf(cB, fabsf(e), d);
                e = fmaf(cA, e, f);
                gg[i] = e + tn;
                cp = tn;
            }
            size_t b0 = (size_t)(blk+1)*32;
#pragma unroll
            for (int i=0;i<32;i++) go[(b0+i)*32 + ch] = gg[i];
        }
    }
}

// ----------------------- freeverb: shared-memory rings ----------------------
// comb ring 2048 (+16 mirror for contiguous FIR reads), allpass ring 1024.
// One __syncthreads per 224-sample chunk; ring aliasing safe (collision needs
// L+j in (1825,2048], max is 1632; allpass window [2,779] mod 1024 != 0).
#define CRING 2048
#define CROW  (CRING + NTAP)
#define ARING 1024
#define SM_BYTES ((8*CROW + 4*ARING) * 4)

__global__ void __launch_bounds__(RCH) k_reverb(){
    extern __shared__ float sm[];
    float* rc = sm;                 // 8 x CROW
    float* ra = sm + 8*CROW;        // 4 x ARING
    const int Lc[8] = {1116,1188,1277,1356,1422,1491,1557,1617};
    const int La[4] = {556,441,341,225};

    int ch = blockIdx.x, tid = threadIdx.x;
    for (int i = tid; i < 8*CROW + 4*ARING; i += RCH) sm[i] = 0.f;
    __syncthreads();

    float fb   = g_vrb[ch][0], damp = g_vrb[ch][1];
    float wet1 = g_vrb[ch][2], dryg = g_vrb[ch][3];
    float fbd  = fb*(1.f - damp);
    const float K2 = 0.16609640474436813f; // log2(10)/20
    const float* __restrict__ yb = g_buf1 + (size_t)ch*T;
    const float* __restrict__ gb = g_buf3;
    float* __restrict__ ob = g_buf2 + (size_t)ch*T;

    for (int c = 0; c < NRC; c++){
        int t = c*RCH + tid;
        if (t < T){
            float xc = yb[t] * exp2f(gb[(size_t)t*32 + ch]*K2);
            float inp = xc*0.015f;
            float acc = 0.f;
            int wp = t & (CRING-1);
#pragma unroll
            for (int k=0;k<8;k++){
                float* w = rc + k*CROW;
                int p0 = (t - Lc[k] - (NTAP-1)) & (CRING-1);
                float s = 0.f;
#pragma unroll
                for (int j=0;j<NTAP;j++) s = fmaf(s, damp, w[p0 + j]);
                float outv = w[p0 + NTAP - 1];
                acc += outv;
                float nv = fmaf(fbd, s, inp);
                w[wp] = nv;
                if (wp < NTAP) w[CRING + wp] = nv;   // mirror
            }
#pragma unroll
            for (int k=0;k<4;k++){
                float* v = ra + k*ARING;
                float bufv = v[(t - La[k]) & (ARING-1)];
                v[t & (ARING-1)] = fmaf(bufv, 0.5f, acc);
                acc = bufv - acc;
            }
            ob[t] = acc*wet1 + xc*dryg;
        }
        __syncthreads();
    }
}

// --------------------------------- mix -------------------------------------
__global__ void k_mix(float* __restrict__ out){
    int idx = blockIdx.x*blockDim.x + threadIdx.x;   // over 4*T
    if (idx >= 4*T) return;
    int b = idx / T, t = idx - b*T;
    float l=0.f, r=0.f;
#pragma unroll
    for (int n=0;n<8;n++){
        int ch = b*8 + n;
        float v = g_buf2[(size_t)ch*T + t];
        l = fmaf(v, g_pg[ch][0], l);
        r = fmaf(v, g_pg[ch][1], r);
    }
    out[((size_t)(b*2+0))*T + t] = l;
    out[((size_t)(b*2+1))*T + t] = r;
}

// -------------------------------- launch ------------------------------------
extern "C" void kernel_launch(void* const* d_in, const int* in_sizes, int n_in,
                              void* d_out, int out_size){
    const float* x = (const float*)d_in[0];
    const float* p = (const float*)d_in[1];
    if (n_in >= 2 && in_sizes[0] < in_sizes[1]) { // defensive: x is the big one
        const float* tmp = x; x = p; p = tmp;
    }
    float* out  = (float*)d_out;
    float* pout = (out_size >= 4*2*T + 4*8*24) ? out + (size_t)4*2*T : nullptr;

    static int smem_set = 0;
    if (!smem_set){
        cudaFuncSetAttribute(k_reverb, cudaFuncAttributeMaxDynamicSharedMemorySize, SM_BYTES);
        smem_set = 1;
    }

    k_params<<<1, 32>>>(p, pout);
    k_biquad<<<NCH, 256>>>(x);
    k_comp<<<1, 32>>>();
    k_reverb<<<NCH, RCH, SM_BYTES>>>();
    k_mix<<<(4*T + 255)/256, 256>>>(out);
}

// round 14
// speedup vs baseline: 2.7809x; 1.3220x over previous
#include <cuda_runtime.h>
#include <math.h>

#define T    65536
#define NCH  32
#define CS   256        // biquad chunk
#define NC   (T/CS)     // 256 chunks
#define ACH  224        // allpass chunk (< min allpass lag 225)
#define NAC  ((T + ACH - 1)/ACH)   // 293
#define CCH  1024       // comb chunk
#define NCC  (T/CCH)    // 64
#define CRING 4096
#define ARING 1024

// ------------------------------- scratch -----------------------------------
__device__ float g_buf1[(size_t)NCH*T];              // y [ch][t] -> xc [ch][t] (in place)
__device__ float g_buf2[(size_t)NCH*T + 32*68];      // tgt [t][32] (+pad) -> reverb out [ch][t]
__device__ float g_buf3[(size_t)NCH*T];              // compressor gain g [t][32]
__device__ float g_buf4[(size_t)NCH*T];              // tgt [ch][t] -> comb acc [ch][t]

__device__ float g_coef[NCH][6][5];            // b0 b1 b2 a1 a2
__device__ float g_P[NCH][144];                // A^256
__device__ float g_gin[NCH];
__device__ float g_cmp[NCH][4];                // a_att a_rel thr slope
__device__ float g_vrb[NCH][4];                // fb damp wet1 dryg
__device__ float g_pg[NCH][2];                 // gout*cos gout*sin

// ------------------------------- params ------------------------------------
__device__ void d_shelf(double fc,double g,double s,double*B,double*A){
    const double SR=44100.0, PI=3.14159265358979323846;
    double Aa=pow(10.0,g/40.0), w=2.0*PI*fc/SR, cw=cos(w);
    double al=sin(w)*0.7071067811865476, sq=2.0*sqrt(Aa)*al;
    B[0]=Aa*((Aa+1.0)+s*(Aa-1.0)*cw+sq);
    B[1]=-2.0*s*Aa*((Aa-1.0)+s*(Aa+1.0)*cw);
    B[2]=Aa*((Aa+1.0)+s*(Aa-1.0)*cw-sq);
    A[0]=(Aa+1.0)-s*(Aa-1.0)*cw+sq;
    A[1]=2.0*s*((Aa-1.0)-s*(Aa+1.0)*cw);
    A[2]=(Aa+1.0)-s*(Aa-1.0)*cw-sq;
}
__device__ void d_peak(double fc,double g,double q,double*B,double*A){
    const double SR=44100.0, PI=3.14159265358979323846;
    double Aa=pow(10.0,g/40.0), w=2.0*PI*fc/SR, cw=cos(w), al=sin(w)/(2.0*q);
    B[0]=1.0+al*Aa; B[1]=-2.0*cw; B[2]=1.0-al*Aa;
    A[0]=1.0+al/Aa; A[1]=-2.0*cw; A[2]=1.0-al/Aa;
}

__global__ void k_params(const float* __restrict__ p, float* __restrict__ pout){
    int ch = threadIdx.x; if (ch >= NCH) return;
    const float* pf = p + ch*24;
    const double SR=44100.0, PI=3.14159265358979323846;
    double gin_db=(double)pf[0]*60.0-48.0;
    double hp=(double)pf[1]*350.0, lp=3000.0+(double)pf[2]*19000.0;
    double hsf=1500.0+(double)pf[3]*14500.0, hsg=(double)pf[4]*30.0-15.0;
    double lsf=30.0+(double)pf[5]*420.0,    lsg=(double)pf[6]*30.0-15.0;
    double mhf=600.0+(double)pf[7]*6400.0,  mhg=(double)pf[8]*30.0-15.0, mhq=0.5+(double)pf[9]*2.5;
    double mlf=200.0+(double)pf[10]*2300.0, mlg=(double)pf[11]*30.0-15.0, mlq=0.5+(double)pf[12]*2.5;
    double cth=-20.0+(double)pf[13]*30.0, crt=1.0+(double)pf[14]*19.0;
    double cat=1.0+(double)pf[15]*29.0,   crl=100.0+(double)pf[16]*3900.0;
    double god=(double)pf[22]*60.0-48.0,  pan=0.3+(double)pf[23]*0.4;

    double B[6][3], A[6][3];
    { double K=tan(PI*hp/SR),a1=(K-1.0)/(K+1.0),b0=1.0/(1.0+K);
      B[0][0]=b0;B[0][1]=-b0;B[0][2]=0;A[0][0]=1;A[0][1]=a1;A[0][2]=0; }
    { double K=tan(PI*lp/SR),a1=(K-1.0)/(K+1.0),b0=K/(1.0+K);
      B[1][0]=b0;B[1][1]=b0;B[1][2]=0;A[1][0]=1;A[1][1]=a1;A[1][2]=0; }
    d_shelf(hsf,hsg, 1.0,B[2],A[2]);
    d_shelf(lsf,lsg,-1.0,B[3],A[3]);
    d_peak (mhf,mhg,mhq,B[4],A[4]);
    d_peak (mlf,mlg,mlq,B[5],A[5]);

    double nb[6][3], na[6][2];
    for (int s=0;s<6;s++){
        double a0=A[s][0];
        float b0=(float)(B[s][0]/a0),b1=(float)(B[s][1]/a0),b2=(float)(B[s][2]/a0);
        float a1=(float)(A[s][1]/a0),a2=(float)(A[s][2]/a0);
        g_coef[ch][s][0]=b0;g_coef[ch][s][1]=b1;g_coef[ch][s][2]=b2;
        g_coef[ch][s][3]=a1;g_coef[ch][s][4]=a2;
        nb[s][0]=b0;nb[s][1]=b1;nb[s][2]=b2;na[s][0]=a1;na[s][1]=a2;
    }
    // one-step 12x12 state map via unit vectors (input = 0)
    float M[144], Tm[144];
    for (int k=0;k<12;k++){
        double z[12]; for(int i=0;i<12;i++) z[i]=0.0; z[k]=1.0;
        double s=0.0;
        for (int sc=0;sc<6;sc++){
            double y =nb[sc][0]*s+z[2*sc];
            double z1=nb[sc][1]*s-na[sc][0]*y+z[2*sc+1];
            double z2=nb[sc][2]*s-na[sc][1]*y;
            z[2*sc]=z1; z[2*sc+1]=z2; s=y;
        }
        for (int r=0;r<12;r++) M[r*12+k]=(float)z[r];
    }
    for (int it=0; it<8; it++){       // M = M^2, 8x -> A^256
        for (int r=0;r<12;r++) for(int c=0;c<12;c++){
            float acc=0.f;
            for (int k=0;k<12;k++) acc=fmaf(M[r*12+k],M[k*12+c],acc);
            Tm[r*12+c]=acc;
        }
        for (int i=0;i<144;i++) M[i]=Tm[i];
    }
    for (int i=0;i<144;i++) g_P[ch][i]=M[i];

    g_gin[ch]=(float)pow(10.0,gin_db/20.0);
    g_cmp[ch][0]=(float)exp(-1.0/(cat*0.001*SR));  // a_att
    g_cmp[ch][1]=(float)exp(-1.0/(crl*0.001*SR));  // a_rel
    g_cmp[ch][2]=(float)cth;
    g_cmp[ch][3]=(float)(1.0-1.0/crt);

    g_vrb[ch][0]=(float)((double)pf[17]*0.28+0.7);
    g_vrb[ch][1]=(float)((double)pf[18]*0.4);
    g_vrb[ch][2]=(float)(3.0*(double)pf[19]*0.5*(1.0+(double)pf[21]));
    g_vrb[ch][3]=(float)(2.0*(double)pf[20]);

    double gol=pow(10.0,god/20.0), th=pan*PI*0.5;
    g_pg[ch][0]=(float)(gol*cos(th));
    g_pg[ch][1]=(float)(gol*sin(th));

    if (pout){
        float* po=pout+ch*24;
        po[0]=(float)gin_db; po[1]=(float)hp; po[2]=(float)lp; po[3]=(float)hsf;
        po[4]=(float)hsg; po[5]=(float)lsf; po[6]=(float)lsg; po[7]=(float)mhf;
        po[8]=(float)mhg; po[9]=(float)mhq; po[10]=(float)mlf; po[11]=(float)mlg;
        po[12]=(float)mlq; po[13]=(float)cth; po[14]=(float)crt; po[15]=(float)cat;
        po[16]=(float)crl; po[17]=pf[17]; po[18]=pf[18]; po[19]=pf[19];
        po[20]=pf[20]; po[21]=pf[21]; po[22]=(float)god; po[23]=(float)pan;
    }
}

// --------------------------- biquad blocked scan ----------------------------
__device__ __forceinline__ float bq6(float s, float z[12], const float c[6][5]){
#pragma unroll
    for (int k=0;k<6;k++){
        float y  = fmaf(c[k][0], s, z[2*k]);
        float z1 = fmaf(c[k][1], s, z[2*k+1]) - c[k][3]*y;
        z[2*k+1] = fmaf(c[k][2], s, -(c[k][4]*y));
        z[2*k]   = z1;
        s = y;
    }
    return s;
}

__global__ void __launch_bounds__(256) k_biquad(const float* __restrict__ x){
    __shared__ float sF[NC][12];
    __shared__ float sI[NC][12];
    int ch = blockIdx.x, tid = threadIdx.x;
    float c[6][5];
#pragma unroll
    for (int k=0;k<6;k++)
#pragma unroll
        for (int j=0;j<5;j++) c[k][j]=g_coef[ch][k][j];
    float gin = g_gin[ch];
    float thr = g_cmp[ch][2], slope = g_cmp[ch][3];
    const float4* xc = (const float4*)(x + (size_t)ch*T) + tid*(CS/4);

    float z[12];
#pragma unroll
    for (int i=0;i<12;i++) z[i]=0.f;
    for (int i=0;i<CS/4;i++){
        float4 v = xc[i];
        bq6(v.x*gin,z,c); bq6(v.y*gin,z,c); bq6(v.z*gin,z,c); bq6(v.w*gin,z,c);
    }
#pragma unroll
    for (int i=0;i<12;i++) sF[tid][i]=z[i];
    __syncthreads();

    if (tid < 12){
        int r = tid;
        float Pr[12];
#pragma unroll
        for (int k=0;k<12;k++) Pr[k]=g_P[ch][r*12+k];
        sI[0][r]=0.f;
        __syncwarp(0xFFFu);
        for (int j=0;j<NC-1;j++){
            float acc = sF[j][r];
#pragma unroll
            for (int k=0;k<12;k++) acc = fmaf(Pr[k], sI[j][k], acc);
            __syncwarp(0xFFFu);
            sI[j+1][r]=acc;
            __syncwarp(0xFFFu);
        }
    }
    __syncthreads();

#pragma unroll
    for (int i=0;i<12;i++) z[i]=sI[tid][i];
    int t0 = tid*CS;
    float* yb = g_buf1 + (size_t)ch*T + t0;
    float* tb = g_buf4 + (size_t)ch*T + t0;
    for (int i=0;i<CS/4;i++){
        float4 v = xc[i];
        float y0=bq6(v.x*gin,z,c), y1=bq6(v.y*gin,z,c);
        float y2=bq6(v.z*gin,z,c), y3=bq6(v.w*gin,z,c);
        ((float4*)yb)[i] = make_float4(y0,y1,y2,y3);
        float ys[4], tg[4];
        ys[0]=y0; ys[1]=y1; ys[2]=y2; ys[3]=y3;
#pragma unroll
        for (int q=0;q<4;q++){
            float lvl = __log2f(fabsf(ys[q]) + 1e-6f) * 6.0205999132796239f;
            tg[q] = fminf(0.f, (thr - lvl)*slope);
        }
        ((float4*)tb)[i] = make_float4(tg[0],tg[1],tg[2],tg[3]);
    }
}

// -------------------- transpose tgt [ch][t] -> [t][32] -----------------------
__global__ void k_tr1(){
    __shared__ float tile[32][33];
    int t0 = blockIdx.x*32;
    int tx = threadIdx.x, ty = threadIdx.y;
    tile[ty][tx] = g_buf4[(size_t)ty*T + t0 + tx];
    __syncthreads();
    g_buf2[(size_t)(t0+ty)*32 + tx] = tile[tx][ty];
}

// ---------------- compressor: EXACT serial scan, 8-cycle chain ---------------
// e' = cA*e + cB*|e| + (tgt_t - tgt_{t+1}) ; g_t = e' + tgt_{t+1}
__global__ void k_comp(){
    int ch = threadIdx.x;
    float aA = g_cmp[ch][0], aR = g_cmp[ch][1];
    float cA = 0.5f*(aA+aR), cB = 0.5f*(aA-aR);
    const float* __restrict__ tg = g_buf2;
    float* __restrict__ go = g_buf3;

    float bufA[32], bufB[32];
#pragma unroll
    for (int i=0;i<32;i++) bufA[i] = tg[(size_t)(i+1)*32 + ch];
    float cp = tg[ch];
    float e  = -cp;
    const int NB = T/32;

    for (int blk = 0; blk < NB; blk += 2){
        {
            size_t base = (size_t)(blk+1)*32 + 1;
#pragma unroll
            for (int i=0;i<32;i++) bufB[i] = tg[(base+i)*32 + ch];
        }
        {
            float gg[32];
#pragma unroll
            for (int i=0;i<32;i++){
                float tn = bufA[i];
                float d  = cp - tn;
                float f  = fmaf(cB, fabsf(e), d);
                e = fmaf(cA, e, f);
                gg[i] = e + tn;
                cp = tn;
            }
            size_t b0 = (size_t)blk*32;
#pragma unroll
            for (int i=0;i<32;i++) go[(b0+i)*32 + ch] = gg[i];
        }
        {
            size_t base = (size_t)(blk+2)*32 + 1;
#pragma unroll
            for (int i=0;i<32;i++) bufA[i] = tg[(base+i)*32 + ch];
        }
        {
            float gg[32];
#pragma unroll
            for (int i=0;i<32;i++){
                float tn = bufB[i];
                float d  = cp - tn;
                float f  = fmaf(cB, fabsf(e), d);
                e = fmaf(cA, e, f);
                gg[i] = e + tn;
                cp = tn;
            }
            size_t b0 = (size_t)(blk+1)*32;
#pragma unroll
            for (int i=0;i<32;i++) go[(b0+i)*32 + ch] = gg[i];
        }
    }
}

// ------------- apply gain: xc[ch][t] = y * 2^(g*K2)  (tiled transpose) -------
__global__ void k_xc(){
    __shared__ float tile[32][33];
    int t0 = blockIdx.x*32;
    int tx = threadIdx.x, ty = threadIdx.y;
    tile[ty][tx] = g_buf3[(size_t)(t0+ty)*32 + tx];  // g row t0+ty, lane=ch
    __syncthreads();
    const float K2 = 0.16609640474436813f; // log2(10)/20
    size_t idx = (size_t)ty*T + t0 + tx;             // ch=ty, t=t0+tx
    g_buf1[idx] = g_buf1[idx] * exp2f(tile[tx][ty]*K2);
}

// --------------------- combs: shuffle-scan damp state ------------------------
// s_t = damp*s_{t-1} + (1-damp)*w[t-L] ; w[t] = inp + fb*s_t ; acc = sum w[t-L]
// 4-step decayed scan = exact 16-tap window (damp<=0.4 -> damp^16=4e-7).
__global__ void __launch_bounds__(CCH) k_comb(){
    extern __shared__ float sm[];
    float* ring  = sm;                       // 8*CRING
    float* fin   = sm + 8*CRING;             // 8*32
    float* carry = fin + 8*32;               // 8
    const int Lc[8] = {1116,1188,1277,1356,1422,1491,1557,1617};

    int ch = blockIdx.x, tid = threadIdx.x;
    int lane = tid & 31, w = tid >> 5;
    for (int i = tid; i < 8*CRING + 8*32 + 8; i += CCH) sm[i] = 0.f;
    __syncthreads();

    float fb = g_vrb[ch][0], damp = g_vrb[ch][1];
    float omd = 1.f - damp;
    float d1 = damp, d2 = d1*d1, d4 = d2*d2, d8 = d4*d4;
    float dl = powf(damp, (float)(lane+1));
    const float* __restrict__ xb = g_buf1 + (size_t)ch*T;
    float* __restrict__ ab = g_buf4 + (size_t)ch*T;

    for (int c = 0; c < NCC; c++){
        int t = c*CCH + tid;
        float inp = 0.015f * xb[t];
        float acc = 0.f;
        float sreg[8];
        float seed0[8];
        // phase 1: load, local scan, publish warp finals
#pragma unroll
        for (int k=0;k<8;k++){
            float wv = ring[k*CRING + ((t - Lc[k]) & (CRING-1))];
            float s = omd * wv;
            float v;
            v = __shfl_up_sync(0xFFFFFFFFu, s, 1); if (lane >= 1) s = fmaf(d1, v, s);
            v = __shfl_up_sync(0xFFFFFFFFu, s, 2); if (lane >= 2) s = fmaf(d2, v, s);
            v = __shfl_up_sync(0xFFFFFFFFu, s, 4); if (lane >= 4) s = fmaf(d4, v, s);
            v = __shfl_up_sync(0xFFFFFFFFu, s, 8); if (lane >= 8) s = fmaf(d8, v, s);
            if (lane == 31) fin[k*32 + w] = s;
            seed0[k] = carry[k];          // stable during phase 1
            sreg[k] = s;
            acc += wv;
        }
        __syncthreads();
        // phase 2: seed, write ring + carries
#pragma unroll
        for (int k=0;k<8;k++){
            float seed = (w == 0) ? seed0[k] : fin[k*32 + (w-1)];
            float s = fmaf(dl, seed, sreg[k]);
            ring[k*CRING + (t & (CRING-1))] = fmaf(fb, s, inp);
            if (tid == CCH-1) carry[k] = s;
        }
        ab[t] = acc;
        __syncthreads();
    }
}

// ----------------------- allpass chain + wet/dry out -------------------------
__global__ void __launch_bounds__(ACH) k_ap(){
    __shared__ float ring[4*ARING];
    const int La[4] = {556,441,341,225};
    int ch = blockIdx.x, tid = threadIdx.x;
    for (int i = tid; i < 4*ARING; i += ACH) ring[i] = 0.f;
    __syncthreads();

    float wet1 = g_vrb[ch][2], dryg = g_vrb[ch][3];
    const float* __restrict__ accb = g_buf4 + (size_t)ch*T;
    const float* __restrict__ xb   = g_buf1 + (size_t)ch*T;
    float* __restrict__ ob         = g_buf2 + (size_t)ch*T;

    float a   = (tid < T) ? accb[tid] : 0.f;
    float xcv = (tid < T) ? xb[tid]   : 0.f;
    for (int c = 0; c < NAC; c++){
        int t = c*ACH + tid;
        int tn = t + ACH;
        float a2  = (tn < T) ? accb[tn] : 0.f;   // prefetch next chunk
        float xc2 = (tn < T) ? xb[tn]   : 0.f;
        if (t < T){
#pragma unroll
            for (int k=0;k<4;k++){
                float bufv = ring[k*ARING + ((t - La[k]) & (ARING-1))];
                ring[k*ARING + (t & (ARING-1))] = fmaf(bufv, 0.5f, a);
                a = bufv - a;
            }
            ob[t] = a*wet1 + xcv*dryg;
        }
        a = a2; xcv = xc2;
        __syncthreads();
    }
}

// --------------------------------- mix -------------------------------------
__global__ void k_mix(float* __restrict__ out){
    int idx = blockIdx.x*blockDim.x + threadIdx.x;   // over 4*T
    if (idx >= 4*T) return;
    int b = idx / T, t = idx - b*T;
    float l=0.f, r=0.f;
#pragma unroll
    for (int n=0;n<8;n++){
        int ch = b*8 + n;
        float v = g_buf2[(size_t)ch*T + t];
        l = fmaf(v, g_pg[ch][0], l);
        r = fmaf(v, g_pg[ch][1], r);
    }
    out[((size_t)(b*2+0))*T + t] = l;
    out[((size_t)(b*2+1))*T + t] = r;
}

// -------------------------------- launch ------------------------------------
#define COMB_SM ((8*CRING + 8*32 + 8)*4)

extern "C" void kernel_launch(void* const* d_in, const int* in_sizes, int n_in,
                              void* d_out, int out_size){
    const float* x = (const float*)d_in[0];
    const float* p = (const float*)d_in[1];
    if (n_in >= 2 && in_sizes[0] < in_sizes[1]) {
        const float* tmp = x; x = p; p = tmp;
    }
    float* out  = (float*)d_out;
    float* pout = (out_size >= 4*2*T + 4*8*24) ? out + (size_t)4*2*T : nullptr;

    static int smem_set = 0;
    if (!smem_set){
        cudaFuncSetAttribute(k_comb, cudaFuncAttributeMaxDynamicSharedMemorySize, COMB_SM);
        smem_set = 1;
    }

    dim3 b32(32,32);
    k_params<<<1, 32>>>(p, pout);
    k_biquad<<<NCH, 256>>>(x);
    k_tr1<<<T/32, b32>>>();
    k_comp<<<1, 32>>>();
    k_xc<<<T/32, b32>>>();
    k_comb<<<NCH, CCH, COMB_SM>>>();
    k_ap<<<NCH, ACH>>>();
    k_mix<<<(4*T + 255)/256, 256>>>(out);
}

// round 15
// speedup vs baseline: 3.0133x; 1.0835x over previous
#include <cuda_runtime.h>
#include <math.h>

#define T    65536
#define NCH  32
#define CS   256        // biquad chunk
#define NC   (T/CS)     // 256 chunks
#define ACH  224        // allpass chunk (< min allpass lag 225)
#define NAC  ((T + ACH - 1)/ACH)   // 293
#define CCH  1024       // comb chunk
#define NCC  (T/CCH)    // 64
#define CRING 4096
#define ARING 1024
#define SEG   32        // compressor segment length
#define NSEG  (T/SEG)   // 2048
#define MROW  36        // padded pieces per (seg,ch): 33 used

// ------------------------------- scratch -----------------------------------
__device__ float g_buf1[(size_t)NCH*T];              // y [ch][t] -> xc [ch][t] (in place)
__device__ float g_buf2[(size_t)NCH*T + 32*68];      // tgt [t][32] (+zero pad) -> reverb out [ch][t]
__device__ float g_buf3[(size_t)NCH*T];              // compressor gain g [t][32]
__device__ float g_buf4[(size_t)NCH*T];              // tgt [ch][t] -> comb acc [ch][t]
__device__ float g_maps[(size_t)(NSEG+8)*NCH*MROW];  // segment map intercepts C_k
__device__ float g_e0[(size_t)NSEG*NCH];             // segment boundary states

__device__ float g_coef[NCH][6][5];            // b0 b1 b2 a1 a2
__device__ float g_P[NCH][144];                // A^256
__device__ float g_gin[NCH];
__device__ float g_cmp[NCH][4];                // a_att a_rel thr slope
__device__ float g_K[NCH][33];                 // K_k = aA^k * aR^(32-k)
__device__ float g_vrb[NCH][4];                // fb damp wet1 dryg
__device__ float g_pg[NCH][2];                 // gout*cos gout*sin

// ------------------------------- params ------------------------------------
__device__ void d_shelf(double fc,double g,double s,double*B,double*A){
    const double SR=44100.0, PI=3.14159265358979323846;
    double Aa=pow(10.0,g/40.0), w=2.0*PI*fc/SR, cw=cos(w);
    double al=sin(w)*0.7071067811865476, sq=2.0*sqrt(Aa)*al;
    B[0]=Aa*((Aa+1.0)+s*(Aa-1.0)*cw+sq);
    B[1]=-2.0*s*Aa*((Aa-1.0)+s*(Aa+1.0)*cw);
    B[2]=Aa*((Aa+1.0)+s*(Aa-1.0)*cw-sq);
    A[0]=(Aa+1.0)-s*(Aa-1.0)*cw+sq;
    A[1]=2.0*s*((Aa-1.0)-s*(Aa+1.0)*cw);
    A[2]=(Aa+1.0)-s*(Aa-1.0)*cw-sq;
}
__device__ void d_peak(double fc,double g,double q,double*B,double*A){
    const double SR=44100.0, PI=3.14159265358979323846;
    double Aa=pow(10.0,g/40.0), w=2.0*PI*fc/SR, cw=cos(w), al=sin(w)/(2.0*q);
    B[0]=1.0+al*Aa; B[1]=-2.0*cw; B[2]=1.0-al*Aa;
    A[0]=1.0+al/Aa; A[1]=-2.0*cw; A[2]=1.0-al/Aa;
}

__global__ void k_params(const float* __restrict__ p, float* __restrict__ pout){
    int ch = threadIdx.x; if (ch >= NCH) return;
    const float* pf = p + ch*24;
    const double SR=44100.0, PI=3.14159265358979323846;
    double gin_db=(double)pf[0]*60.0-48.0;
    double hp=(double)pf[1]*350.0, lp=3000.0+(double)pf[2]*19000.0;
    double hsf=1500.0+(double)pf[3]*14500.0, hsg=(double)pf[4]*30.0-15.0;
    double lsf=30.0+(double)pf[5]*420.0,    lsg=(double)pf[6]*30.0-15.0;
    double mhf=600.0+(double)pf[7]*6400.0,  mhg=(double)pf[8]*30.0-15.0, mhq=0.5+(double)pf[9]*2.5;
    double mlf=200.0+(double)pf[10]*2300.0, mlg=(double)pf[11]*30.0-15.0, mlq=0.5+(double)pf[12]*2.5;
    double cth=-20.0+(double)pf[13]*30.0, crt=1.0+(double)pf[14]*19.0;
    double cat=1.0+(double)pf[15]*29.0,   crl=100.0+(double)pf[16]*3900.0;
    double god=(double)pf[22]*60.0-48.0,  pan=0.3+(double)pf[23]*0.4;

    double B[6][3], A[6][3];
    { double K=tan(PI*hp/SR),a1=(K-1.0)/(K+1.0),b0=1.0/(1.0+K);
      B[0][0]=b0;B[0][1]=-b0;B[0][2]=0;A[0][0]=1;A[0][1]=a1;A[0][2]=0; }
    { double K=tan(PI*lp/SR),a1=(K-1.0)/(K+1.0),b0=K/(1.0+K);
      B[1][0]=b0;B[1][1]=b0;B[1][2]=0;A[1][0]=1;A[1][1]=a1;A[1][2]=0; }
    d_shelf(hsf,hsg, 1.0,B[2],A[2]);
    d_shelf(lsf,lsg,-1.0,B[3],A[3]);
    d_peak (mhf,mhg,mhq,B[4],A[4]);
    d_peak (mlf,mlg,mlq,B[5],A[5]);

    double nb[6][3], na[6][2];
    for (int s=0;s<6;s++){
        double a0=A[s][0];
        float b0=(float)(B[s][0]/a0),b1=(float)(B[s][1]/a0),b2=(float)(B[s][2]/a0);
        float a1=(float)(A[s][1]/a0),a2=(float)(A[s][2]/a0);
        g_coef[ch][s][0]=b0;g_coef[ch][s][1]=b1;g_coef[ch][s][2]=b2;
        g_coef[ch][s][3]=a1;g_coef[ch][s][4]=a2;
        nb[s][0]=b0;nb[s][1]=b1;nb[s][2]=b2;na[s][0]=a1;na[s][1]=a2;
    }
    // one-step 12x12 state map via unit vectors (input = 0)
    float M[144], Tm[144];
    for (int k=0;k<12;k++){
        double z[12]; for(int i=0;i<12;i++) z[i]=0.0; z[k]=1.0;
        double s=0.0;
        for (int sc=0;sc<6;sc++){
            double y =nb[sc][0]*s+z[2*sc];
            double z1=nb[sc][1]*s-na[sc][0]*y+z[2*sc+1];
            double z2=nb[sc][2]*s-na[sc][1]*y;
            z[2*sc]=z1; z[2*sc+1]=z2; s=y;
        }
        for (int r=0;r<12;r++) M[r*12+k]=(float)z[r];
    }
    for (int it=0; it<8; it++){       // M = M^2, 8x -> A^256
        for (int r=0;r<12;r++) for(int c=0;c<12;c++){
            float acc=0.f;
            for (int k=0;k<12;k++) acc=fmaf(M[r*12+k],M[k*12+c],acc);
            Tm[r*12+c]=acc;
        }
        for (int i=0;i<144;i++) M[i]=Tm[i];
    }
    for (int i=0;i<144;i++) g_P[ch][i]=M[i];

    g_gin[ch]=(float)pow(10.0,gin_db/20.0);
    double aat=exp(-1.0/(cat*0.001*SR)), arl=exp(-1.0/(crl*0.001*SR));
    g_cmp[ch][0]=(float)aat;
    g_cmp[ch][1]=(float)arl;
    g_cmp[ch][2]=(float)cth;
    g_cmp[ch][3]=(float)(1.0-1.0/crt);
    for (int k=0;k<=32;k++)
        g_K[ch][k]=(float)(pow(aat,(double)k)*pow(arl,(double)(32-k)));

    g_vrb[ch][0]=(float)((double)pf[17]*0.28+0.7);
    g_vrb[ch][1]=(float)((double)pf[18]*0.4);
    g_vrb[ch][2]=(float)(3.0*(double)pf[19]*0.5*(1.0+(double)pf[21]));
    g_vrb[ch][3]=(float)(2.0*(double)pf[20]);

    double gol=pow(10.0,god/20.0), th=pan*PI*0.5;
    g_pg[ch][0]=(float)(gol*cos(th));
    g_pg[ch][1]=(float)(gol*sin(th));

    if (pout){
        float* po=pout+ch*24;
        po[0]=(float)gin_db; po[1]=(float)hp; po[2]=(float)lp; po[3]=(float)hsf;
        po[4]=(float)hsg; po[5]=(float)lsf; po[6]=(float)lsg; po[7]=(float)mhf;
        po[8]=(float)mhg; po[9]=(float)mhq; po[10]=(float)mlf; po[11]=(float)mlg;
        po[12]=(float)mlq; po[13]=(float)cth; po[14]=(float)crt; po[15]=(float)cat;
        po[16]=(float)crl; po[17]=pf[17]; po[18]=pf[18]; po[19]=pf[19];
        po[20]=pf[20]; po[21]=pf[21]; po[22]=(float)god; po[23]=(float)pan;
    }
}

// --------------------------- biquad blocked scan ----------------------------
__device__ __forceinline__ float bq6(float s, float z[12], const float c[6][5]){
#pragma unroll
    for (int k=0;k<6;k++){
        float y  = fmaf(c[k][0], s, z[2*k]);
        float z1 = fmaf(c[k][1], s, z[2*k+1]) - c[k][3]*y;
        z[2*k+1] = fmaf(c[k][2], s, -(c[k][4]*y));
        z[2*k]   = z1;
        s = y;
    }
    return s;
}

__global__ void __launch_bounds__(256) k_biquad(const float* __restrict__ x){
    __shared__ float sF[NC][12];
    __shared__ float sI[NC][12];
    int ch = blockIdx.x, tid = threadIdx.x;
    float c[6][5];
#pragma unroll
    for (int k=0;k<6;k++)
#pragma unroll
        for (int j=0;j<5;j++) c[k][j]=g_coef[ch][k][j];
    float gin = g_gin[ch];
    float thr = g_cmp[ch][2], slope = g_cmp[ch][3];
    const float4* xc = (const float4*)(x + (size_t)ch*T) + tid*(CS/4);

    float z[12];
#pragma unroll
    for (int i=0;i<12;i++) z[i]=0.f;
    for (int i=0;i<CS/4;i++){
        float4 v = xc[i];
        bq6(v.x*gin,z,c); bq6(v.y*gin,z,c); bq6(v.z*gin,z,c); bq6(v.w*gin,z,c);
    }
#pragma unroll
    for (int i=0;i<12;i++) sF[tid][i]=z[i];
    __syncthreads();

    if (tid < 12){
        int r = tid;
        float Pr[12];
#pragma unroll
        for (int k=0;k<12;k++) Pr[k]=g_P[ch][r*12+k];
        sI[0][r]=0.f;
        __syncwarp(0xFFFu);
        for (int j=0;j<NC-1;j++){
            float acc = sF[j][r];
#pragma unroll
            for (int k=0;k<12;k++) acc = fmaf(Pr[k], sI[j][k], acc);
            __syncwarp(0xFFFu);
            sI[j+1][r]=acc;
            __syncwarp(0xFFFu);
        }
    }
    __syncthreads();

#pragma unroll
    for (int i=0;i<12;i++) z[i]=sI[tid][i];
    int t0 = tid*CS;
    float* yb = g_buf1 + (size_t)ch*T + t0;
    float* tb = g_buf4 + (size_t)ch*T + t0;
    for (int i=0;i<CS/4;i++){
        float4 v = xc[i];
        float y0=bq6(v.x*gin,z,c), y1=bq6(v.y*gin,z,c);
        float y2=bq6(v.z*gin,z,c), y3=bq6(v.w*gin,z,c);
        ((float4*)yb)[i] = make_float4(y0,y1,y2,y3);
        float ys[4], tg[4];
        ys[0]=y0; ys[1]=y1; ys[2]=y2; ys[3]=y3;
#pragma unroll
        for (int q=0;q<4;q++){
            float lvl = __log2f(fabsf(ys[q]) + 1e-6f) * 6.0205999132796239f;
            tg[q] = fminf(0.f, (thr - lvl)*slope);
        }
        ((float4*)tb)[i] = make_float4(tg[0],tg[1],tg[2],tg[3]);
    }
}

// -------------------- transpose tgt [ch][t] -> [t][32] -----------------------
__global__ void k_tr1(){
    __shared__ float tile[32][33];
    int t0 = blockIdx.x*32;
    int tx = threadIdx.x, ty = threadIdx.y;
    tile[ty][tx] = g_buf4[(size_t)ty*T + t0 + tx];
    __syncthreads();
    g_buf2[(size_t)(t0+ty)*32 + tx] = tile[tx][ty];
}

// ============== compressor: EXACT min-affine segment decomposition ==========
// step: e' = min(aA*e + d, aR*e + d)   (aA < aR always => min realizes the
// attack/release selection exactly).  32-step segment map is concave PL:
// h(e) = min_{k=0..32}( K_k*e + C_k ),  K_k = aA^k aR^(32-k),
// C_k by DP:  C_k <- min(aA*C_{k-1} + d_t, aR*C_k + d_t)  (descending k).

// Phase A: build segment maps (warp per segment, lane = channel)
__global__ void __launch_bounds__(256) k_cmapA(){
    int ch = threadIdx.x & 31;
    int s  = blockIdx.x*8 + (threadIdx.x >> 5);
    float aA = g_cmp[ch][0], aR = g_cmp[ch][1];
    const float* __restrict__ tg = g_buf2;

    float C[33];
    C[0] = 0.f;
#pragma unroll
    for (int k=1;k<33;k++) C[k] = 1e30f;
    int tb = s*SEG;
    float T0 = tg[(size_t)tb*32 + ch];
    for (int t=0;t<SEG;t++){
        float T1 = tg[(size_t)(tb+t+1)*32 + ch];
        float d = T0 - T1;
#pragma unroll
        for (int k=32;k>=1;k--)
            C[k] = fminf(fmaf(aA, C[k-1], d), fmaf(aR, C[k], d));
        C[0] = fmaf(aR, C[0], d);
        T0 = T1;
    }
    float* o = g_maps + ((size_t)s*NCH + ch)*MROW;
#pragma unroll
    for (int k=0;k<33;k++) o[k] = C[k];
}

// min over 33 candidates, tree depth 6
__device__ __forceinline__ float min33(float* v){
#pragma unroll
    for (int i=0;i<16;i++) v[i] = fminf(v[i], v[i+16]);
#pragma unroll
    for (int i=0;i<8;i++)  v[i] = fminf(v[i], v[i+8]);
#pragma unroll
    for (int i=0;i<4;i++)  v[i] = fminf(v[i], v[i+4]);
    v[0] = fminf(v[0], v[2]); v[1] = fminf(v[1], v[3]);
    return fminf(fminf(v[0], v[1]), v[32]);
}

// Phase B: serial boundary pass (1 warp, lane = channel), 4-deep prefetch
__global__ void __launch_bounds__(32) k_cmapB(){
    int ch = threadIdx.x;
    float K[33];
#pragma unroll
    for (int k=0;k<33;k++) K[k] = g_K[ch][k];
    const float* __restrict__ mp = g_maps;
    float* __restrict__ e0 = g_e0;
    float e = -g_buf2[ch];

    float4 b0[9], b1[9], b2[9], b3[9];
    size_t row = (size_t)ch*MROW;
#pragma unroll
    for (int j=0;j<9;j++){
        b0[j] = *(const float4*)(mp + ((size_t)0*NCH*MROW) + row + 4*j);
        b1[j] = *(const float4*)(mp + ((size_t)1*NCH*MROW) + row + 4*j);
        b2[j] = *(const float4*)(mp + ((size_t)2*NCH*MROW) + row + 4*j);
    }
    for (int s=0; s<NSEG; s+=4){
        float cand[33];
        // load s+3, eval b0
#pragma unroll
        for (int j=0;j<9;j++) b3[j] = *(const float4*)(mp + ((size_t)(s+3)*NCH*MROW) + row + 4*j);
        e0[(size_t)s*32 + ch] = e;
#pragma unroll
        for (int k=0;k<33;k++) cand[k] = fmaf(K[k], e, ((const float*)b0)[k]);
        e = min33(cand);
        // load s+4, eval b1
#pragma unroll
        for (int j=0;j<9;j++) b0[j] = *(const float4*)(mp + ((size_t)(s+4)*NCH*MROW) + row + 4*j);
        e0[(size_t)(s+1)*32 + ch] = e;
#pragma unroll
        for (int k=0;k<33;k++) cand[k] = fmaf(K[k], e, ((const float*)b1)[k]);
        e = min33(cand);
        // load s+5, eval b2
#pragma unroll
        for (int j=0;j<9;j++) b1[j] = *(const float4*)(mp + ((size_t)(s+5)*NCH*MROW) + row + 4*j);
        e0[(size_t)(s+2)*32 + ch] = e;
#pragma unroll
        for (int k=0;k<33;k++) cand[k] = fmaf(K[k], e, ((const float*)b2)[k]);
        e = min33(cand);
        // load s+6, eval b3
#pragma unroll
        for (int j=0;j<9;j++) b2[j] = *(const float4*)(mp + ((size_t)(s+6)*NCH*MROW) + row + 4*j);
        e0[(size_t)(s+3)*32 + ch] = e;
#pragma unroll
        for (int k=0;k<33;k++) cand[k] = fmaf(K[k], e, ((const float*)b3)[k]);
        e = min33(cand);
    }
}

// Phase C: exact within-segment rerun (warp per segment, lane = channel)
__global__ void __launch_bounds__(256) k_cmapC(){
    int ch = threadIdx.x & 31;
    int s  = blockIdx.x*8 + (threadIdx.x >> 5);
    float aA = g_cmp[ch][0], aR = g_cmp[ch][1];
    const float* __restrict__ tg = g_buf2;
    float* __restrict__ go = g_buf3;

    float e = g_e0[(size_t)s*32 + ch];
    int tb = s*SEG;
    float T0 = tg[(size_t)tb*32 + ch];
#pragma unroll
    for (int i=0;i<SEG;i++){
        float T1 = tg[(size_t)(tb+i+1)*32 + ch];
        float d = T0 - T1;
        e = fminf(fmaf(aA, e, d), fmaf(aR, e, d));
        go[(size_t)(tb+i)*32 + ch] = e + T1;
        T0 = T1;
    }
}

// ------------- apply gain: xc[ch][t] = y * 2^(g*K2)  (tiled transpose) -------
__global__ void k_xc(){
    __shared__ float tile[32][33];
    int t0 = blockIdx.x*32;
    int tx = threadIdx.x, ty = threadIdx.y;
    tile[ty][tx] = g_buf3[(size_t)(t0+ty)*32 + tx];
    __syncthreads();
    const float K2 = 0.16609640474436813f; // log2(10)/20
    size_t idx = (size_t)ty*T + t0 + tx;
    g_buf1[idx] = g_buf1[idx] * exp2f(tile[tx][ty]*K2);
}

// --------------------- combs: shuffle-scan damp state ------------------------
__global__ void __launch_bounds__(CCH) k_comb(){
    extern __shared__ float sm[];
    float* ring  = sm;                       // 8*CRING
    float* fin   = sm + 8*CRING;             // 8*32
    float* carry = fin + 8*32;               // 8
    const int Lc[8] = {1116,1188,1277,1356,1422,1491,1557,1617};

    int ch = blockIdx.x, tid = threadIdx.x;
    int lane = tid & 31, w = tid >> 5;
    for (int i = tid; i < 8*CRING + 8*32 + 8; i += CCH) sm[i] = 0.f;
    __syncthreads();

    float fb = g_vrb[ch][0], damp = g_vrb[ch][1];
    float omd = 1.f - damp;
    float d1 = damp, d2 = d1*d1, d4 = d2*d2, d8 = d4*d4;
    float dl = powf(damp, (float)(lane+1));
    const float* __restrict__ xb = g_buf1 + (size_t)ch*T;
    float* __restrict__ ab = g_buf4 + (size_t)ch*T;

    for (int c = 0; c < NCC; c++){
        int t = c*CCH + tid;
        float inp = 0.015f * xb[t];
        float acc = 0.f;
        float sreg[8];
        float seed0[8];
#pragma unroll
        for (int k=0;k<8;k++){
            float wv = ring[k*CRING + ((t - Lc[k]) & (CRING-1))];
            float s = omd * wv;
            float v;
            v = __shfl_up_sync(0xFFFFFFFFu, s, 1); if (lane >= 1) s = fmaf(d1, v, s);
            v = __shfl_up_sync(0xFFFFFFFFu, s, 2); if (lane >= 2) s = fmaf(d2, v, s);
            v = __shfl_up_sync(0xFFFFFFFFu, s, 4); if (lane >= 4) s = fmaf(d4, v, s);
            v = __shfl_up_sync(0xFFFFFFFFu, s, 8); if (lane >= 8) s = fmaf(d8, v, s);
            if (lane == 31) fin[k*32 + w] = s;
            seed0[k] = carry[k];
            sreg[k] = s;
            acc += wv;
        }
        __syncthreads();
#pragma unroll
        for (int k=0;k<8;k++){
            float seed = (w == 0) ? seed0[k] : fin[k*32 + (w-1)];
            float s = fmaf(dl, seed, sreg[k]);
            ring[k*CRING + (t & (CRING-1))] = fmaf(fb, s, inp);
            if (tid == CCH-1) carry[k] = s;
        }
        ab[t] = acc;
        __syncthreads();
    }
}

// ----------------------- allpass chain + wet/dry out -------------------------
__global__ void __launch_bounds__(ACH) k_ap(){
    __shared__ float ring[4*ARING];
    const int La[4] = {556,441,341,225};
    int ch = blockIdx.x, tid = threadIdx.x;
    for (int i = tid; i < 4*ARING; i += ACH) ring[i] = 0.f;
    __syncthreads();

    float wet1 = g_vrb[ch][2], dryg = g_vrb[ch][3];
    const float* __restrict__ accb = g_buf4 + (size_t)ch*T;
    const float* __restrict__ xb   = g_buf1 + (size_t)ch*T;
    float* __restrict__ ob         = g_buf2 + (size_t)ch*T;

    float a   = accb[tid];
    float xcv = xb[tid];
    for (int c = 0; c < NAC; c++){
        int t = c*ACH + tid;
        int tn = t + ACH;
        float a2  = (tn < T) ? accb[tn] : 0.f;
        float xc2 = (tn < T) ? xb[tn]   : 0.f;
        if (t < T){
#pragma unroll
            for (int k=0;k<4;k++){
                float bufv = ring[k*ARING + ((t - La[k]) & (ARING-1))];
                ring[k*ARING + (t & (ARING-1))] = fmaf(bufv, 0.5f, a);
                a = bufv - a;
            }
            ob[t] = a*wet1 + xcv*dryg;
        }
        a = a2; xcv = xc2;
        __syncthreads();
    }
}

// --------------------------------- mix -------------------------------------
__global__ void k_mix(float* __restrict__ out){
    int idx = blockIdx.x*blockDim.x + threadIdx.x;   // over 4*T
    if (idx >= 4*T) return;
    int b = idx / T, t = idx - b*T;
    float l=0.f, r=0.f;
#pragma unroll
    for (int n=0;n<8;n++){
        int ch = b*8 + n;
        float v = g_buf2[(size_t)ch*T + t];
        l = fmaf(v, g_pg[ch][0], l);
        r = fmaf(v, g_pg[ch][1], r);
    }
    out[((size_t)(b*2+0))*T + t] = l;
    out[((size_t)(b*2+1))*T + t] = r;
}

// -------------------------------- launch ------------------------------------
#define COMB_SM ((8*CRING + 8*32 + 8)*4)

extern "C" void kernel_launch(void* const* d_in, const int* in_sizes, int n_in,
                              void* d_out, int out_size){
    const float* x = (const float*)d_in[0];
    const float* p = (const float*)d_in[1];
    if (n_in >= 2 && in_sizes[0] < in_sizes[1]) {
        const float* tmp = x; x = p; p = tmp;
    }
    float* out  = (float*)d_out;
    float* pout = (out_size >= 4*2*T + 4*8*24) ? out + (size_t)4*2*T : nullptr;

    static int smem_set = 0;
    if (!smem_set){
        cudaFuncSetAttribute(k_comb, cudaFuncAttributeMaxDynamicSharedMemorySize, COMB_SM);
        smem_set = 1;
    }

    dim3 b32(32,32);
    k_params<<<1, 32>>>(p, pout);
    k_biquad<<<NCH, 256>>>(x);
    k_tr1<<<T/32, b32>>>();
    k_cmapA<<<NSEG/8, 256>>>();
    k_cmapB<<<1, 32>>>();
    k_cmapC<<<NSEG/8, 256>>>();
    k_xc<<<T/32, b32>>>();
    k_comb<<<NCH, CCH, COMB_SM>>>();
    k_ap<<<NCH, ACH>>>();
    k_mix<<<(4*T + 255)/256, 256>>>(out);
}